// round 1
// baseline (speedup 1.0000x reference)
#include <cuda_runtime.h>
#include <math.h>

#define EMBED 1024
#define HEADS 16
#define HEAD_DIM 64
#define HIDDEN 4096
#define BATCH 2
#define SEQ 2048
#define NTOK (BATCH*SEQ)   // 4096
#define EPS 1e-6f

// ---------------- scratch (device globals; no allocation) ----------------
__device__ float g_xn  [NTOK * EMBED];     // layernorm outputs (reused)
__device__ float g_qkv [NTOK * 3 * EMBED]; // qkv projections
__device__ float g_att [NTOK * EMBED];     // attention output
__device__ float g_x1  [NTOK * EMBED];     // x after attention residual
__device__ float g_h   [NTOK * HIDDEN];    // fc1 output

// ---------------- LayerNorm ----------------
__global__ void __launch_bounds__(256) ln_kernel(const float* __restrict__ in,
                                                 const float* __restrict__ w,
                                                 const float* __restrict__ b,
                                                 float* __restrict__ out)
{
    __shared__ float red[8];
    __shared__ float s_mu, s_rs;
    int row = blockIdx.x;
    int tid = threadIdx.x;
    const float4* ip = (const float4*)(in + (size_t)row * EMBED);
    float4 v = ip[tid];

    float s = v.x + v.y + v.z + v.w;
    #pragma unroll
    for (int o = 16; o; o >>= 1) s += __shfl_xor_sync(0xffffffffu, s, o);
    if ((tid & 31) == 0) red[tid >> 5] = s;
    __syncthreads();
    if (tid == 0) {
        float tot = 0.f;
        #pragma unroll
        for (int i = 0; i < 8; i++) tot += red[i];
        s_mu = tot * (1.0f / EMBED);
    }
    __syncthreads();
    float mu = s_mu;

    float dx = v.x - mu, dy = v.y - mu, dz = v.z - mu, dw = v.w - mu;
    float s2 = dx*dx + dy*dy + dz*dz + dw*dw;
    #pragma unroll
    for (int o = 16; o; o >>= 1) s2 += __shfl_xor_sync(0xffffffffu, s2, o);
    __syncthreads();              // protect red[] reuse
    if ((tid & 31) == 0) red[tid >> 5] = s2;
    __syncthreads();
    if (tid == 0) {
        float tot = 0.f;
        #pragma unroll
        for (int i = 0; i < 8; i++) tot += red[i];
        s_rs = rsqrtf(tot * (1.0f / EMBED) + EPS);
    }
    __syncthreads();
    float rs = s_rs;

    float4 wv = ((const float4*)w)[tid];
    float4 bv = ((const float4*)b)[tid];
    float4 o4;
    o4.x = dx * rs * wv.x + bv.x;
    o4.y = dy * rs * wv.y + bv.y;
    o4.z = dz * rs * wv.z + bv.z;
    o4.w = dw * rs * wv.w + bv.w;
    ((float4*)(out + (size_t)row * EMBED))[tid] = o4;
}

// ---------------- SGEMM (NT): C[m,n] = sum_k A[m,k]*B[n,k] + bias[n] (+epilogue)
// EPI: 0 = bias, 1 = bias + residual, 2 = bias + exact GELU
template<int EPI>
__global__ void __launch_bounds__(256) sgemm_nt(const float* __restrict__ A,
                                                const float* __restrict__ B,
                                                const float* __restrict__ bias,
                                                const float* __restrict__ res,
                                                float* __restrict__ C,
                                                int M, int N, int K)
{
    __shared__ float As[16][128];
    __shared__ float Bs[16][128];

    int tid = threadIdx.x;
    int bm = blockIdx.y * 128;
    int bn = blockIdx.x * 128;
    int ty = tid >> 4;          // 0..15
    int tx = tid & 15;          // 0..15

    float acc[8][8];
    #pragma unroll
    for (int i = 0; i < 8; i++)
        #pragma unroll
        for (int j = 0; j < 8; j++) acc[i][j] = 0.f;

    int lr = tid >> 1;          // 0..127
    int lk = (tid & 1) * 8;     // 0 or 8
    const float* Ap = A + (size_t)(bm + lr) * K + lk;
    const float* Bp = B + (size_t)(bn + lr) * K + lk;

    for (int k0 = 0; k0 < K; k0 += 16) {
        float4 a0 = *(const float4*)(Ap + k0);
        float4 a1 = *(const float4*)(Ap + k0 + 4);
        float4 b0 = *(const float4*)(Bp + k0);
        float4 b1 = *(const float4*)(Bp + k0 + 4);
        __syncthreads();
        As[lk+0][lr] = a0.x; As[lk+1][lr] = a0.y; As[lk+2][lr] = a0.z; As[lk+3][lr] = a0.w;
        As[lk+4][lr] = a1.x; As[lk+5][lr] = a1.y; As[lk+6][lr] = a1.z; As[lk+7][lr] = a1.w;
        Bs[lk+0][lr] = b0.x; Bs[lk+1][lr] = b0.y; Bs[lk+2][lr] = b0.z; Bs[lk+3][lr] = b0.w;
        Bs[lk+4][lr] = b1.x; Bs[lk+5][lr] = b1.y; Bs[lk+6][lr] = b1.z; Bs[lk+7][lr] = b1.w;
        __syncthreads();
        #pragma unroll
        for (int kk = 0; kk < 16; kk++) {
            float ar[8], br[8];
            *(float4*)(ar)     = *(const float4*)&As[kk][ty*8];
            *(float4*)(ar + 4) = *(const float4*)&As[kk][ty*8 + 4];
            *(float4*)(br)     = *(const float4*)&Bs[kk][tx*8];
            *(float4*)(br + 4) = *(const float4*)&Bs[kk][tx*8 + 4];
            #pragma unroll
            for (int i = 0; i < 8; i++)
                #pragma unroll
                for (int j = 0; j < 8; j++)
                    acc[i][j] += ar[i] * br[j];
        }
    }

    // epilogue
    float bv[8];
    *(float4*)(bv)     = *(const float4*)(bias + bn + tx*8);
    *(float4*)(bv + 4) = *(const float4*)(bias + bn + tx*8 + 4);

    #pragma unroll
    for (int i = 0; i < 8; i++) {
        int row = bm + ty*8 + i;
        size_t base = (size_t)row * N + bn + tx*8;
        float v[8];
        #pragma unroll
        for (int j = 0; j < 8; j++) v[j] = acc[i][j] + bv[j];
        if (EPI == 1) {
            float4 r0 = *(const float4*)(res + base);
            float4 r1 = *(const float4*)(res + base + 4);
            v[0]+=r0.x; v[1]+=r0.y; v[2]+=r0.z; v[3]+=r0.w;
            v[4]+=r1.x; v[5]+=r1.y; v[6]+=r1.z; v[7]+=r1.w;
        }
        if (EPI == 2) {
            #pragma unroll
            for (int j = 0; j < 8; j++)
                v[j] = 0.5f * v[j] * (1.0f + erff(v[j] * 0.70710678118654752f));
        }
        float4 o0 = make_float4(v[0], v[1], v[2], v[3]);
        float4 o1 = make_float4(v[4], v[5], v[6], v[7]);
        *(float4*)(C + base)     = o0;
        *(float4*)(C + base + 4) = o1;
    }
}

// ---------------- Flash attention (fp32, causal) ----------------
// grid: (SEQ/64, HEADS, BATCH), block 256.
// Thread (r = tid/4, j = tid%4): owns query row r, output dims [j*16, j*16+16),
// and score columns c = 4t + j (t = 0..15).
#define AS 68   // padded smem row stride

__global__ void __launch_bounds__(256) attn_kernel(const float* __restrict__ qkv,
                                                   float* __restrict__ out)
{
    extern __shared__ float sm[];
    float* Qs = sm;
    float* Ks = Qs + 64 * AS;
    float* Vs = Ks + 64 * AS;
    float* Ps = Vs + 64 * AS;

    int tid = threadIdx.x;
    int b = blockIdx.z, h = blockIdx.y;
    int q0 = blockIdx.x * 64;
    int r = tid >> 2;
    int j = tid & 3;

    const float scale = 0.125f;   // 1/sqrt(64)

    // load Q (scaled)
    {
        int lr = tid >> 2, c0 = (tid & 3) * 16;
        const float* qp = qkv + (size_t)(b * SEQ + q0 + lr) * 3072 + h * 64 + c0;
        float* dst = Qs + lr * AS + c0;
        #pragma unroll
        for (int i = 0; i < 16; i += 4) {
            float4 v = *(const float4*)(qp + i);
            v.x *= scale; v.y *= scale; v.z *= scale; v.w *= scale;
            *(float4*)(dst + i) = v;
        }
    }

    float m = -INFINITY, l = 0.f;
    float o[16];
    #pragma unroll
    for (int i = 0; i < 16; i++) o[i] = 0.f;

    int ntiles = blockIdx.x + 1;
    int qr = q0 + r;

    for (int kt = 0; kt < ntiles; kt++) {
        int k0 = kt * 64;
        __syncthreads();   // protect Ks/Vs/Ps reuse from previous iteration
        {
            int lr = tid >> 2, c0 = (tid & 3) * 16;
            const float* kp = qkv + (size_t)(b * SEQ + k0 + lr) * 3072 + EMBED + h * 64 + c0;
            const float* vp = kp + EMBED;
            float* kd = Ks + lr * AS + c0;
            float* vd = Vs + lr * AS + c0;
            #pragma unroll
            for (int i = 0; i < 16; i += 4) {
                *(float4*)(kd + i) = *(const float4*)(kp + i);
                *(float4*)(vd + i) = *(const float4*)(vp + i);
            }
        }
        __syncthreads();

        // scores: s[t] = Q[r,:] . K[4t+j,:]
        float s[16];
        #pragma unroll
        for (int t = 0; t < 16; t++) s[t] = 0.f;
        #pragma unroll 4
        for (int d = 0; d < 64; d += 4) {
            float4 qv = *(const float4*)&Qs[r * AS + d];
            #pragma unroll
            for (int t = 0; t < 16; t++) {
                float4 kv = *(const float4*)&Ks[(4*t + j) * AS + d];
                s[t] += qv.x*kv.x + qv.y*kv.y + qv.z*kv.z + qv.w*kv.w;
            }
        }
        // causal mask
        #pragma unroll
        for (int t = 0; t < 16; t++) {
            int kc = k0 + 4*t + j;
            if (kc > qr) s[t] = -INFINITY;
        }
        // tile max over 64 columns (16 local + reduce over 4 lanes of the row group)
        float tm = s[0];
        #pragma unroll
        for (int t = 1; t < 16; t++) tm = fmaxf(tm, s[t]);
        tm = fmaxf(tm, __shfl_xor_sync(0xffffffffu, tm, 1));
        tm = fmaxf(tm, __shfl_xor_sync(0xffffffffu, tm, 2));

        float mn = fmaxf(m, tm);
        float alpha = __expf(m - mn);
        l *= alpha;
        #pragma unroll
        for (int i = 0; i < 16; i++) o[i] *= alpha;

        float ps = 0.f;
        #pragma unroll
        for (int t = 0; t < 16; t++) {
            float p = __expf(s[t] - mn);
            ps += p;
            Ps[r * AS + 4*t + j] = p;
        }
        ps += __shfl_xor_sync(0xffffffffu, ps, 1);
        ps += __shfl_xor_sync(0xffffffffu, ps, 2);
        l += ps;
        m = mn;
        __syncwarp();

        // O += P @ V   (this thread: dims j*16 .. j*16+15)
        #pragma unroll 4
        for (int c = 0; c < 64; c++) {
            float p = Ps[r * AS + c];
            const float* vrow = &Vs[c * AS + j * 16];
            float4 v0 = *(const float4*)(vrow);
            float4 v1 = *(const float4*)(vrow + 4);
            float4 v2 = *(const float4*)(vrow + 8);
            float4 v3 = *(const float4*)(vrow + 12);
            o[0]  += p * v0.x; o[1]  += p * v0.y; o[2]  += p * v0.z; o[3]  += p * v0.w;
            o[4]  += p * v1.x; o[5]  += p * v1.y; o[6]  += p * v1.z; o[7]  += p * v1.w;
            o[8]  += p * v2.x; o[9]  += p * v2.y; o[10] += p * v2.z; o[11] += p * v2.w;
            o[12] += p * v3.x; o[13] += p * v3.y; o[14] += p * v3.z; o[15] += p * v3.w;
        }
    }

    float inv = 1.0f / l;
    float* op = out + (size_t)(b * SEQ + q0 + r) * EMBED + h * 64 + j * 16;
    #pragma unroll
    for (int i = 0; i < 16; i += 4) {
        float4 v = make_float4(o[i]*inv, o[i+1]*inv, o[i+2]*inv, o[i+3]*inv);
        *(float4*)(op + i) = v;
    }
}

// ---------------- launch ----------------
extern "C" void kernel_launch(void* const* d_in, const int* in_sizes, int n_in,
                              void* d_out, int out_size)
{
    const float* x      = (const float*)d_in[0];
    const float* ln1_w  = (const float*)d_in[1];
    const float* ln1_b  = (const float*)d_in[2];
    const float* qkv_w  = (const float*)d_in[3];
    const float* qkv_b  = (const float*)d_in[4];
    const float* proj_w = (const float*)d_in[5];
    const float* proj_b = (const float*)d_in[6];
    const float* ln2_w  = (const float*)d_in[7];
    const float* ln2_b  = (const float*)d_in[8];
    const float* fc1_w  = (const float*)d_in[9];
    const float* fc1_b  = (const float*)d_in[10];
    const float* fc2_w  = (const float*)d_in[11];
    const float* fc2_b  = (const float*)d_in[12];
    float* out = (float*)d_out;

    float *xn, *qkv, *att, *x1, *hbuf;
    cudaGetSymbolAddress((void**)&xn,   g_xn);
    cudaGetSymbolAddress((void**)&qkv,  g_qkv);
    cudaGetSymbolAddress((void**)&att,  g_att);
    cudaGetSymbolAddress((void**)&x1,   g_x1);
    cudaGetSymbolAddress((void**)&hbuf, g_h);

    int attn_smem = 4 * 64 * AS * sizeof(float);  // 69632
    cudaFuncSetAttribute(attn_kernel, cudaFuncAttributeMaxDynamicSharedMemorySize, attn_smem);

    // 1. LN1
    ln_kernel<<<NTOK, 256>>>(x, ln1_w, ln1_b, xn);
    // 2. QKV = xn @ qkv_w^T + qkv_b          [4096, 3072]
    sgemm_nt<0><<<dim3(3*EMBED/128, NTOK/128), 256>>>(xn, qkv_w, qkv_b, nullptr, qkv,
                                                      NTOK, 3*EMBED, EMBED);
    // 3. attention
    attn_kernel<<<dim3(SEQ/64, HEADS, BATCH), 256, attn_smem>>>(qkv, att);
    // 4. x1 = att @ proj_w^T + proj_b + x    [4096, 1024]
    sgemm_nt<1><<<dim3(EMBED/128, NTOK/128), 256>>>(att, proj_w, proj_b, x, x1,
                                                    NTOK, EMBED, EMBED);
    // 5. LN2
    ln_kernel<<<NTOK, 256>>>(x1, ln2_w, ln2_b, xn);
    // 6. h = gelu(xn @ fc1_w^T + fc1_b)      [4096, 4096]
    sgemm_nt<2><<<dim3(HIDDEN/128, NTOK/128), 256>>>(xn, fc1_w, fc1_b, nullptr, hbuf,
                                                     NTOK, HIDDEN, EMBED);
    // 7. out = h @ fc2_w^T + fc2_b + x1      [4096, 1024]
    sgemm_nt<1><<<dim3(EMBED/128, NTOK/128), 256>>>(hbuf, fc2_w, fc2_b, x1, out,
                                                    NTOK, EMBED, HIDDEN);
}

// round 3
// speedup vs baseline: 1.5802x; 1.5802x over previous
#include <cuda_runtime.h>
#include <cuda_bf16.h>
#include <math.h>
#include <stdint.h>

#define EMBED 1024
#define HEADS 16
#define HEAD_DIM 64
#define HIDDEN 4096
#define BATCH 2
#define SEQ 2048
#define NTOK (BATCH*SEQ)   // 4096
#define EPS 1e-6f

// ================= scratch (device globals; no allocation) =================
__device__ __align__(1024) float g_qkv [NTOK * 3 * EMBED];
__device__ __align__(1024) float g_x1  [NTOK * EMBED];

__device__ __align__(1024) __nv_bfloat16 g_xn_hi [NTOK * EMBED];
__device__ __align__(1024) __nv_bfloat16 g_xn_lo [NTOK * EMBED];
__device__ __align__(1024) __nv_bfloat16 g_att_hi[NTOK * EMBED];
__device__ __align__(1024) __nv_bfloat16 g_att_lo[NTOK * EMBED];
__device__ __align__(1024) __nv_bfloat16 g_h_hi  [NTOK * HIDDEN];
__device__ __align__(1024) __nv_bfloat16 g_h_lo  [NTOK * HIDDEN];

__device__ __align__(1024) __nv_bfloat16 g_qkvw_hi [3*EMBED*EMBED];
__device__ __align__(1024) __nv_bfloat16 g_qkvw_lo [3*EMBED*EMBED];
__device__ __align__(1024) __nv_bfloat16 g_projw_hi[EMBED*EMBED];
__device__ __align__(1024) __nv_bfloat16 g_projw_lo[EMBED*EMBED];
__device__ __align__(1024) __nv_bfloat16 g_fc1w_hi [HIDDEN*EMBED];
__device__ __align__(1024) __nv_bfloat16 g_fc1w_lo [HIDDEN*EMBED];
__device__ __align__(1024) __nv_bfloat16 g_fc2w_hi [EMBED*HIDDEN];
__device__ __align__(1024) __nv_bfloat16 g_fc2w_lo [EMBED*HIDDEN];

// ================= helpers =================
__device__ __forceinline__ uint32_t smem_u32(const void* p) {
    uint32_t a;
    asm("{ .reg .u64 t; cvta.to.shared.u64 t, %1; cvt.u32.u64 %0, t; }" : "=r"(a) : "l"(p));
    return a;
}
#define CP16(dst, src) \
    asm volatile("cp.async.cg.shared.global [%0], [%1], 16;" :: "r"(dst), "l"(src) : "memory")
#define CP_COMMIT() asm volatile("cp.async.commit_group;" ::: "memory")

#define SWZ(x) ((x) ^ (((x) >> 3) & 0x70))

__device__ __forceinline__ void ldsm_x4(uint32_t addr, uint32_t& r0, uint32_t& r1,
                                        uint32_t& r2, uint32_t& r3) {
    asm volatile("ldmatrix.sync.aligned.m8n8.x4.shared.b16 {%0,%1,%2,%3}, [%4];"
                 : "=r"(r0), "=r"(r1), "=r"(r2), "=r"(r3) : "r"(addr));
}
__device__ __forceinline__ void mma16816(float* d, const uint32_t* a, const uint32_t* b) {
    asm volatile("mma.sync.aligned.m16n8k16.row.col.f32.bf16.bf16.f32 "
        "{%0,%1,%2,%3}, {%4,%5,%6,%7}, {%8,%9}, {%0,%1,%2,%3};"
        : "+f"(d[0]), "+f"(d[1]), "+f"(d[2]), "+f"(d[3])
        : "r"(a[0]), "r"(a[1]), "r"(a[2]), "r"(a[3]), "r"(b[0]), "r"(b[1]));
}

__device__ __forceinline__ uint32_t f2bf2(float a, float b) {
    __nv_bfloat162 t = __floats2bfloat162_rn(a, b);
    return *(uint32_t*)&t;
}
__device__ __forceinline__ void split2(float x, float y, uint32_t& ph, uint32_t& pl) {
    __nv_bfloat16 hx = __float2bfloat16(x), hy = __float2bfloat16(y);
    ph = f2bf2(__bfloat162float(hx), __bfloat162float(hy));
    pl = f2bf2(x - __bfloat162float(hx), y - __bfloat162float(hy));
}
__device__ __forceinline__ void split4(float x, float y, float z, float w,
                                       uint2& ph, uint2& pl) {
    split2(x, y, ph.x, pl.x);
    split2(z, w, ph.y, pl.y);
}

// ================= weight fp32 -> bf16 hi/lo =================
__global__ void __launch_bounds__(256) cvt_kernel(const float* __restrict__ in,
                                                  __nv_bfloat16* __restrict__ hi,
                                                  __nv_bfloat16* __restrict__ lo,
                                                  int n4)
{
    int i = blockIdx.x * 256 + threadIdx.x;
    if (i >= n4) return;
    float4 v = ((const float4*)in)[i];
    uint2 ph, pl;
    split4(v.x, v.y, v.z, v.w, ph, pl);
    ((uint2*)hi)[i] = ph;
    ((uint2*)lo)[i] = pl;
}

// ================= LayerNorm -> bf16 hi/lo =================
__global__ void __launch_bounds__(256) ln_kernel(const float* __restrict__ in,
                                                 const float* __restrict__ w,
                                                 const float* __restrict__ b,
                                                 __nv_bfloat16* __restrict__ ohi,
                                                 __nv_bfloat16* __restrict__ olo)
{
    __shared__ float red[8];
    __shared__ float s_mu, s_rs;
    int row = blockIdx.x;
    int tid = threadIdx.x;
    const float4* ip = (const float4*)(in + (size_t)row * EMBED);
    float4 v = ip[tid];

    float s = v.x + v.y + v.z + v.w;
    #pragma unroll
    for (int o = 16; o; o >>= 1) s += __shfl_xor_sync(0xffffffffu, s, o);
    if ((tid & 31) == 0) red[tid >> 5] = s;
    __syncthreads();
    if (tid == 0) {
        float tot = 0.f;
        #pragma unroll
        for (int i = 0; i < 8; i++) tot += red[i];
        s_mu = tot * (1.0f / EMBED);
    }
    __syncthreads();
    float mu = s_mu;

    float dx = v.x - mu, dy = v.y - mu, dz = v.z - mu, dw = v.w - mu;
    float s2 = dx*dx + dy*dy + dz*dz + dw*dw;
    #pragma unroll
    for (int o = 16; o; o >>= 1) s2 += __shfl_xor_sync(0xffffffffu, s2, o);
    __syncthreads();
    if ((tid & 31) == 0) red[tid >> 5] = s2;
    __syncthreads();
    if (tid == 0) {
        float tot = 0.f;
        #pragma unroll
        for (int i = 0; i < 8; i++) tot += red[i];
        s_rs = rsqrtf(tot * (1.0f / EMBED) + EPS);
    }
    __syncthreads();
    float rs = s_rs;

    float4 wv = ((const float4*)w)[tid];
    float4 bv = ((const float4*)b)[tid];
    float ox = dx * rs * wv.x + bv.x;
    float oy = dy * rs * wv.y + bv.y;
    float oz = dz * rs * wv.z + bv.z;
    float ow = dw * rs * wv.w + bv.w;
    uint2 ph, pl;
    split4(ox, oy, oz, ow, ph, pl);
    size_t base = (size_t)row * EMBED + tid * 4;
    *(uint2*)(ohi + base) = ph;
    *(uint2*)(olo + base) = pl;
}

// ================= HMMA GEMM (NT, bf16x3 split, fp32 accum) =================
// C[m,n] = sum_k A[m,k]*B[n,k] + bias[n] (+epilogue)
// EPI: 0 = bias (fp32), 1 = bias + residual (fp32), 2 = bias + gelu (bf16 hi/lo)
#define TILEB 16384   // 128 rows * 128 bytes

template<int EPI>
__global__ void __launch_bounds__(256, 1) mm_kernel(
    const __nv_bfloat16* __restrict__ Ahi, const __nv_bfloat16* __restrict__ Alo,
    const __nv_bfloat16* __restrict__ Bhi, const __nv_bfloat16* __restrict__ Blo,
    const float* __restrict__ bias, const float* __restrict__ res,
    float* __restrict__ C,
    __nv_bfloat16* __restrict__ Chi, __nv_bfloat16* __restrict__ Clo,
    int M, int N, int K)
{
    extern __shared__ char smem[];   // 2 stages * 4 tiles * 16KB = 128KB
    uint32_t sb = smem_u32(smem);
    int tid = threadIdx.x;
    int bm = blockIdx.x * 128;
    int bn = blockIdx.y * 128;
    int lane = tid & 31, w = tid >> 5;
    int wm = w & 1, wn = w >> 1;     // warp grid 2(m) x 4(n)

    // cp.async geometry: cc = 16B column chunk (0..7), r0 = base row (0..31)
    int cc = tid & 7;
    int r0 = tid >> 3;
    const char* pAh = (const char*)(Ahi + (size_t)(bm + r0) * K) + cc * 16;
    const char* pAl = (const char*)(Alo + (size_t)(bm + r0) * K) + cc * 16;
    const char* pBh = (const char*)(Bhi + (size_t)(bn + r0) * K) + cc * 16;
    const char* pBl = (const char*)(Blo + (size_t)(bn + r0) * K) + cc * 16;
    size_t rowblk = (size_t)K * 64;  // 32 rows * K * 2B

    float acc[4][4][4];
    #pragma unroll
    for (int i = 0; i < 4; i++)
        #pragma unroll
        for (int j = 0; j < 4; j++)
            #pragma unroll
            for (int q = 0; q < 4; q++) acc[i][j][q] = 0.f;

    int nCh = K >> 6;

    // prefetch chunk 0
    {
        uint32_t st = sb;
        #pragma unroll
        for (int j = 0; j < 4; j++) {
            uint32_t d = SWZ((uint32_t)((r0 + 32*j) * 128 + cc * 16));
            size_t so = (size_t)j * rowblk;
            CP16(st + 0*TILEB + d, pAh + so);
            CP16(st + 1*TILEB + d, pAl + so);
            CP16(st + 2*TILEB + d, pBh + so);
            CP16(st + 3*TILEB + d, pBl + so);
        }
        CP_COMMIT();
    }

    for (int c = 0; c < nCh; c++) {
        if (c + 1 < nCh) {
            uint32_t st = sb + (uint32_t)((c + 1) & 1) * (4 * TILEB);
            size_t koff = (size_t)(c + 1) * 128;
            #pragma unroll
            for (int j = 0; j < 4; j++) {
                uint32_t d = SWZ((uint32_t)((r0 + 32*j) * 128 + cc * 16));
                size_t so = (size_t)j * rowblk + koff;
                CP16(st + 0*TILEB + d, pAh + so);
                CP16(st + 1*TILEB + d, pAl + so);
                CP16(st + 2*TILEB + d, pBh + so);
                CP16(st + 3*TILEB + d, pBl + so);
            }
            CP_COMMIT();
            asm volatile("cp.async.wait_group 1;" ::: "memory");
        } else {
            asm volatile("cp.async.wait_group 0;" ::: "memory");
        }
        __syncthreads();

        uint32_t st = sb + (uint32_t)(c & 1) * (4 * TILEB);
        uint32_t Ahs = st, Als = st + TILEB, Bhs = st + 2*TILEB, Bls = st + 3*TILEB;

        #pragma unroll
        for (int ks = 0; ks < 4; ks++) {
            uint32_t ahi[4][4], alo[4][4], bhi[4][2], blo[4][2];
            // A fragments: row = wm*64 + i*16 + lane%16, c16 = ks*2 + lane/16
            #pragma unroll
            for (int i = 0; i < 4; i++) {
                int row = wm*64 + i*16 + (lane & 15);
                int c16 = ks*2 + (lane >> 4);
                uint32_t off = SWZ((uint32_t)(row * 128 + c16 * 16));
                ldsm_x4(Ahs + off, ahi[i][0], ahi[i][1], ahi[i][2], ahi[i][3]);
                ldsm_x4(Als + off, alo[i][0], alo[i][1], alo[i][2], alo[i][3]);
            }
            // B fragments: two x4 loads cover 4 n-frags
            #pragma unroll
            for (int jj = 0; jj < 2; jj++) {
                int row = wn*32 + jj*16 + (lane & 7) + (((lane >> 4) & 1) << 3);
                int c16 = ks*2 + ((lane >> 3) & 1);
                uint32_t off = SWZ((uint32_t)(row * 128 + c16 * 16));
                uint32_t t0, t1, t2, t3;
                ldsm_x4(Bhs + off, t0, t1, t2, t3);
                bhi[jj*2][0] = t0; bhi[jj*2][1] = t1;
                bhi[jj*2+1][0] = t2; bhi[jj*2+1][1] = t3;
                ldsm_x4(Bls + off, t0, t1, t2, t3);
                blo[jj*2][0] = t0; blo[jj*2][1] = t1;
                blo[jj*2+1][0] = t2; blo[jj*2+1][1] = t3;
            }
            // three split products, reuse distance 16 on each accumulator
            #pragma unroll
            for (int i = 0; i < 4; i++)
                #pragma unroll
                for (int j = 0; j < 4; j++)
                    mma16816(acc[i][j], ahi[i], bhi[j]);
            #pragma unroll
            for (int i = 0; i < 4; i++)
                #pragma unroll
                for (int j = 0; j < 4; j++)
                    mma16816(acc[i][j], ahi[i], blo[j]);
            #pragma unroll
            for (int i = 0; i < 4; i++)
                #pragma unroll
                for (int j = 0; j < 4; j++)
                    mma16816(acc[i][j], alo[i], bhi[j]);
        }
        __syncthreads();
    }

    // ---- epilogue: direct to gmem ----
    int mrow = bm + wm*64;
    int ncol = bn + wn*32;
    #pragma unroll
    for (int i = 0; i < 4; i++) {
        #pragma unroll
        for (int j = 0; j < 4; j++) {
            int rg = mrow + i*16 + (lane >> 2);
            int cg = ncol + j*8 + 2*(lane & 3);
            float b0v = bias[cg], b1v = bias[cg + 1];
            float v0 = acc[i][j][0] + b0v, v1 = acc[i][j][1] + b1v;
            float v2 = acc[i][j][2] + b0v, v3 = acc[i][j][3] + b1v;
            size_t a0 = (size_t)rg * N + cg;
            size_t a1 = (size_t)(rg + 8) * N + cg;
            if (EPI == 1) {
                float2 q0 = *(const float2*)(res + a0);
                float2 q1 = *(const float2*)(res + a1);
                v0 += q0.x; v1 += q0.y; v2 += q1.x; v3 += q1.y;
            }
            if (EPI == 2) {
                v0 = 0.5f * v0 * (1.0f + erff(v0 * 0.70710678118654752f));
                v1 = 0.5f * v1 * (1.0f + erff(v1 * 0.70710678118654752f));
                v2 = 0.5f * v2 * (1.0f + erff(v2 * 0.70710678118654752f));
                v3 = 0.5f * v3 * (1.0f + erff(v3 * 0.70710678118654752f));
                uint32_t ph, pl;
                split2(v0, v1, ph, pl);
                *(uint32_t*)(Chi + a0) = ph;
                *(uint32_t*)(Clo + a0) = pl;
                split2(v2, v3, ph, pl);
                *(uint32_t*)(Chi + a1) = ph;
                *(uint32_t*)(Clo + a1) = pl;
            } else {
                *(float2*)(C + a0) = make_float2(v0, v1);
                *(float2*)(C + a1) = make_float2(v2, v3);
            }
        }
    }
}

// ================= Flash attention (fp32, causal) — hi/lo epilogue =================
#define AS 68

__global__ void __launch_bounds__(256) attn_kernel(const float* __restrict__ qkv,
                                                   __nv_bfloat16* __restrict__ ohi,
                                                   __nv_bfloat16* __restrict__ olo)
{
    extern __shared__ float sm[];
    float* Qs = sm;
    float* Ks = Qs + 64 * AS;
    float* Vs = Ks + 64 * AS;
    float* Ps = Vs + 64 * AS;

    int tid = threadIdx.x;
    int b = blockIdx.z, h = blockIdx.y;
    int q0 = blockIdx.x * 64;
    int r = tid >> 2;
    int j = tid & 3;

    const float scale = 0.125f;

    {
        int lr = tid >> 2, c0 = (tid & 3) * 16;
        const float* qp = qkv + (size_t)(b * SEQ + q0 + lr) * 3072 + h * 64 + c0;
        float* dst = Qs + lr * AS + c0;
        #pragma unroll
        for (int i = 0; i < 16; i += 4) {
            float4 v = *(const float4*)(qp + i);
            v.x *= scale; v.y *= scale; v.z *= scale; v.w *= scale;
            *(float4*)(dst + i) = v;
        }
    }

    float m = -INFINITY, l = 0.f;
    float o[16];
    #pragma unroll
    for (int i = 0; i < 16; i++) o[i] = 0.f;

    int ntiles = blockIdx.x + 1;
    int qr = q0 + r;

    for (int kt = 0; kt < ntiles; kt++) {
        int k0 = kt * 64;
        __syncthreads();
        {
            int lr = tid >> 2, c0 = (tid & 3) * 16;
            const float* kp = qkv + (size_t)(b * SEQ + k0 + lr) * 3072 + EMBED + h * 64 + c0;
            const float* vp = kp + EMBED;
            float* kd = Ks + lr * AS + c0;
            float* vd = Vs + lr * AS + c0;
            #pragma unroll
            for (int i = 0; i < 16; i += 4) {
                *(float4*)(kd + i) = *(const float4*)(kp + i);
                *(float4*)(vd + i) = *(const float4*)(vp + i);
            }
        }
        __syncthreads();

        float s[16];
        #pragma unroll
        for (int t = 0; t < 16; t++) s[t] = 0.f;
        #pragma unroll 4
        for (int d = 0; d < 64; d += 4) {
            float4 qv = *(const float4*)&Qs[r * AS + d];
            #pragma unroll
            for (int t = 0; t < 16; t++) {
                float4 kv = *(const float4*)&Ks[(4*t + j) * AS + d];
                s[t] += qv.x*kv.x + qv.y*kv.y + qv.z*kv.z + qv.w*kv.w;
            }
        }
        #pragma unroll
        for (int t = 0; t < 16; t++) {
            int kc = k0 + 4*t + j;
            if (kc > qr) s[t] = -INFINITY;
        }
        float tm = s[0];
        #pragma unroll
        for (int t = 1; t < 16; t++) tm = fmaxf(tm, s[t]);
        tm = fmaxf(tm, __shfl_xor_sync(0xffffffffu, tm, 1));
        tm = fmaxf(tm, __shfl_xor_sync(0xffffffffu, tm, 2));

        float mn = fmaxf(m, tm);
        float alpha = __expf(m - mn);
        l *= alpha;
        #pragma unroll
        for (int i = 0; i < 16; i++) o[i] *= alpha;

        float ps = 0.f;
        #pragma unroll
        for (int t = 0; t < 16; t++) {
            float p = __expf(s[t] - mn);
            ps += p;
            Ps[r * AS + 4*t + j] = p;
        }
        ps += __shfl_xor_sync(0xffffffffu, ps, 1);
        ps += __shfl_xor_sync(0xffffffffu, ps, 2);
        l += ps;
        m = mn;
        __syncwarp();

        #pragma unroll 4
        for (int c = 0; c < 64; c++) {
            float p = Ps[r * AS + c];
            const float* vrow = &Vs[c * AS + j * 16];
            float4 v0 = *(const float4*)(vrow);
            float4 v1 = *(const float4*)(vrow + 4);
            float4 v2 = *(const float4*)(vrow + 8);
            float4 v3 = *(const float4*)(vrow + 12);
            o[0]  += p * v0.x; o[1]  += p * v0.y; o[2]  += p * v0.z; o[3]  += p * v0.w;
            o[4]  += p * v1.x; o[5]  += p * v1.y; o[6]  += p * v1.z; o[7]  += p * v1.w;
            o[8]  += p * v2.x; o[9]  += p * v2.y; o[10] += p * v2.z; o[11] += p * v2.w;
            o[12] += p * v3.x; o[13] += p * v3.y; o[14] += p * v3.z; o[15] += p * v3.w;
        }
    }

    float inv = 1.0f / l;
    size_t base = (size_t)(b * SEQ + q0 + r) * EMBED + h * 64 + j * 16;
    #pragma unroll
    for (int i = 0; i < 16; i += 4) {
        uint2 ph, pl;
        split4(o[i]*inv, o[i+1]*inv, o[i+2]*inv, o[i+3]*inv, ph, pl);
        *(uint2*)(ohi + base + i) = ph;
        *(uint2*)(olo + base + i) = pl;
    }
}

// ================= launch =================
extern "C" void kernel_launch(void* const* d_in, const int* in_sizes, int n_in,
                              void* d_out, int out_size)
{
    const float* x      = (const float*)d_in[0];
    const float* ln1_w  = (const float*)d_in[1];
    const float* ln1_b  = (const float*)d_in[2];
    const float* qkv_w  = (const float*)d_in[3];
    const float* qkv_b  = (const float*)d_in[4];
    const float* proj_w = (const float*)d_in[5];
    const float* proj_b = (const float*)d_in[6];
    const float* ln2_w  = (const float*)d_in[7];
    const float* ln2_b  = (const float*)d_in[8];
    const float* fc1_w  = (const float*)d_in[9];
    const float* fc1_b  = (const float*)d_in[10];
    const float* fc2_w  = (const float*)d_in[11];
    const float* fc2_b  = (const float*)d_in[12];
    float* out = (float*)d_out;

    float *qkv, *x1;
    __nv_bfloat16 *xn_hi, *xn_lo, *att_hi, *att_lo, *h_hi, *h_lo;
    __nv_bfloat16 *qw_hi, *qw_lo, *pw_hi, *pw_lo, *f1_hi, *f1_lo, *f2_hi, *f2_lo;
    cudaGetSymbolAddress((void**)&qkv,    g_qkv);
    cudaGetSymbolAddress((void**)&x1,     g_x1);
    cudaGetSymbolAddress((void**)&xn_hi,  g_xn_hi);
    cudaGetSymbolAddress((void**)&xn_lo,  g_xn_lo);
    cudaGetSymbolAddress((void**)&att_hi, g_att_hi);
    cudaGetSymbolAddress((void**)&att_lo, g_att_lo);
    cudaGetSymbolAddress((void**)&h_hi,   g_h_hi);
    cudaGetSymbolAddress((void**)&h_lo,   g_h_lo);
    cudaGetSymbolAddress((void**)&qw_hi,  g_qkvw_hi);
    cudaGetSymbolAddress((void**)&qw_lo,  g_qkvw_lo);
    cudaGetSymbolAddress((void**)&pw_hi,  g_projw_hi);
    cudaGetSymbolAddress((void**)&pw_lo,  g_projw_lo);
    cudaGetSymbolAddress((void**)&f1_hi,  g_fc1w_hi);
    cudaGetSymbolAddress((void**)&f1_lo,  g_fc1w_lo);
    cudaGetSymbolAddress((void**)&f2_hi,  g_fc2w_hi);
    cudaGetSymbolAddress((void**)&f2_lo,  g_fc2w_lo);

    int gemm_smem = 2 * 4 * TILEB;   // 131072
    cudaFuncSetAttribute(mm_kernel<0>, cudaFuncAttributeMaxDynamicSharedMemorySize, gemm_smem);
    cudaFuncSetAttribute(mm_kernel<1>, cudaFuncAttributeMaxDynamicSharedMemorySize, gemm_smem);
    cudaFuncSetAttribute(mm_kernel<2>, cudaFuncAttributeMaxDynamicSharedMemorySize, gemm_smem);
    int attn_smem = 4 * 64 * AS * sizeof(float);
    cudaFuncSetAttribute(attn_kernel, cudaFuncAttributeMaxDynamicSharedMemorySize, attn_smem);

    // weight conversion
    cvt_kernel<<<(3*EMBED*EMBED/4 + 255)/256, 256>>>(qkv_w,  qw_hi, qw_lo, 3*EMBED*EMBED/4);
    cvt_kernel<<<(EMBED*EMBED/4   + 255)/256, 256>>>(proj_w, pw_hi, pw_lo, EMBED*EMBED/4);
    cvt_kernel<<<(HIDDEN*EMBED/4  + 255)/256, 256>>>(fc1_w,  f1_hi, f1_lo, HIDDEN*EMBED/4);
    cvt_kernel<<<(EMBED*HIDDEN/4  + 255)/256, 256>>>(fc2_w,  f2_hi, f2_lo, EMBED*HIDDEN/4);

    // 1. LN1 -> xn hi/lo
    ln_kernel<<<NTOK, 256>>>(x, ln1_w, ln1_b, xn_hi, xn_lo);
    // 2. qkv = xn @ qkv_w^T + qkv_b  (fp32)
    mm_kernel<0><<<dim3(NTOK/128, 3*EMBED/128), 256, gemm_smem>>>(
        xn_hi, xn_lo, qw_hi, qw_lo, qkv_b, nullptr, qkv, nullptr, nullptr,
        NTOK, 3*EMBED, EMBED);
    // 3. attention -> att hi/lo
    attn_kernel<<<dim3(SEQ/64, HEADS, BATCH), 256, attn_smem>>>(qkv, att_hi, att_lo);
    // 4. x1 = att @ proj_w^T + proj_b + x  (fp32)
    mm_kernel<1><<<dim3(NTOK/128, EMBED/128), 256, gemm_smem>>>(
        att_hi, att_lo, pw_hi, pw_lo, proj_b, x, x1, nullptr, nullptr,
        NTOK, EMBED, EMBED);
    // 5. LN2 -> xn hi/lo
    ln_kernel<<<NTOK, 256>>>(x1, ln2_w, ln2_b, xn_hi, xn_lo);
    // 6. h = gelu(xn @ fc1_w^T + fc1_b) -> bf16 hi/lo
    mm_kernel<2><<<dim3(NTOK/128, HIDDEN/128), 256, gemm_smem>>>(
        xn_hi, xn_lo, f1_hi, f1_lo, fc1_b, nullptr, nullptr, h_hi, h_lo,
        NTOK, HIDDEN, EMBED);
    // 7. out = h @ fc2_w^T + fc2_b + x1  (fp32)
    mm_kernel<1><<<dim3(NTOK/128, EMBED/128), 256, gemm_smem>>>(
        h_hi, h_lo, f2_hi, f2_lo, fc2_b, x1, out, nullptr, nullptr,
        NTOK, EMBED, HIDDEN);
}

// round 4
// speedup vs baseline: 4.2380x; 2.6819x over previous
#include <cuda_runtime.h>
#include <cuda_bf16.h>
#include <math.h>
#include <stdint.h>

#define EMBED 1024
#define HEADS 16
#define HEAD_DIM 64
#define HIDDEN 4096
#define BATCH 2
#define SEQ 2048
#define NTOK (BATCH*SEQ)   // 4096
#define EPS 1e-6f
#define QSCALE 0.1803368801111204f   // 1/sqrt(64) * log2(e)

// ================= scratch (device globals; no allocation) =================
__device__ __align__(1024) float g_x1  [NTOK * EMBED];

__device__ __align__(1024) __nv_bfloat16 g_xn_hi [NTOK * EMBED];
__device__ __align__(1024) __nv_bfloat16 g_xn_lo [NTOK * EMBED];
__device__ __align__(1024) __nv_bfloat16 g_qkv_hi[NTOK * 3 * EMBED];
__device__ __align__(1024) __nv_bfloat16 g_qkv_lo[NTOK * 3 * EMBED];
__device__ __align__(1024) __nv_bfloat16 g_att_hi[NTOK * EMBED];
__device__ __align__(1024) __nv_bfloat16 g_att_lo[NTOK * EMBED];
__device__ __align__(1024) __nv_bfloat16 g_h_hi  [NTOK * HIDDEN];
__device__ __align__(1024) __nv_bfloat16 g_h_lo  [NTOK * HIDDEN];

__device__ __align__(1024) __nv_bfloat16 g_qkvw_hi [3*EMBED*EMBED];
__device__ __align__(1024) __nv_bfloat16 g_qkvw_lo [3*EMBED*EMBED];
__device__ __align__(1024) __nv_bfloat16 g_projw_hi[EMBED*EMBED];
__device__ __align__(1024) __nv_bfloat16 g_projw_lo[EMBED*EMBED];
__device__ __align__(1024) __nv_bfloat16 g_fc1w_hi [HIDDEN*EMBED];
__device__ __align__(1024) __nv_bfloat16 g_fc1w_lo [HIDDEN*EMBED];
__device__ __align__(1024) __nv_bfloat16 g_fc2w_hi [EMBED*HIDDEN];
__device__ __align__(1024) __nv_bfloat16 g_fc2w_lo [EMBED*HIDDEN];

// ================= helpers =================
__device__ __forceinline__ uint32_t smem_u32(const void* p) {
    uint32_t a;
    asm("{ .reg .u64 t; cvta.to.shared.u64 t, %1; cvt.u32.u64 %0, t; }" : "=r"(a) : "l"(p));
    return a;
}
#define CP16(dst, src) \
    asm volatile("cp.async.cg.shared.global [%0], [%1], 16;" :: "r"(dst), "l"(src) : "memory")
#define CP_COMMIT() asm volatile("cp.async.commit_group;" ::: "memory")

#define SWZ(x) ((x) ^ (((x) >> 3) & 0x70))

__device__ __forceinline__ void ldsm_x4(uint32_t addr, uint32_t& r0, uint32_t& r1,
                                        uint32_t& r2, uint32_t& r3) {
    asm volatile("ldmatrix.sync.aligned.m8n8.x4.shared.b16 {%0,%1,%2,%3}, [%4];"
                 : "=r"(r0), "=r"(r1), "=r"(r2), "=r"(r3) : "r"(addr));
}
__device__ __forceinline__ void ldsm_x4_t(uint32_t addr, uint32_t& r0, uint32_t& r1,
                                          uint32_t& r2, uint32_t& r3) {
    asm volatile("ldmatrix.sync.aligned.m8n8.x4.trans.shared.b16 {%0,%1,%2,%3}, [%4];"
                 : "=r"(r0), "=r"(r1), "=r"(r2), "=r"(r3) : "r"(addr));
}
__device__ __forceinline__ void mma16816(float* d, const uint32_t* a, const uint32_t* b) {
    asm volatile("mma.sync.aligned.m16n8k16.row.col.f32.bf16.bf16.f32 "
        "{%0,%1,%2,%3}, {%4,%5,%6,%7}, {%8,%9}, {%0,%1,%2,%3};"
        : "+f"(d[0]), "+f"(d[1]), "+f"(d[2]), "+f"(d[3])
        : "r"(a[0]), "r"(a[1]), "r"(a[2]), "r"(a[3]), "r"(b[0]), "r"(b[1]));
}
__device__ __forceinline__ float ex2f(float x) {
    float y; asm("ex2.approx.f32 %0, %1;" : "=f"(y) : "f"(x)); return y;
}

__device__ __forceinline__ uint32_t f2bf2(float a, float b) {
    __nv_bfloat162 t = __floats2bfloat162_rn(a, b);
    return *(uint32_t*)&t;
}
__device__ __forceinline__ void split2(float x, float y, uint32_t& ph, uint32_t& pl) {
    __nv_bfloat16 hx = __float2bfloat16(x), hy = __float2bfloat16(y);
    ph = f2bf2(__bfloat162float(hx), __bfloat162float(hy));
    pl = f2bf2(x - __bfloat162float(hx), y - __bfloat162float(hy));
}
__device__ __forceinline__ void split4(float x, float y, float z, float w,
                                       uint2& ph, uint2& pl) {
    split2(x, y, ph.x, pl.x);
    split2(z, w, ph.y, pl.y);
}

// ================= weight fp32 -> bf16 hi/lo =================
__global__ void __launch_bounds__(256) cvt_kernel(const float* __restrict__ in,
                                                  __nv_bfloat16* __restrict__ hi,
                                                  __nv_bfloat16* __restrict__ lo,
                                                  int n4)
{
    int i = blockIdx.x * 256 + threadIdx.x;
    if (i >= n4) return;
    float4 v = ((const float4*)in)[i];
    uint2 ph, pl;
    split4(v.x, v.y, v.z, v.w, ph, pl);
    ((uint2*)hi)[i] = ph;
    ((uint2*)lo)[i] = pl;
}

// ================= LayerNorm -> bf16 hi/lo =================
__global__ void __launch_bounds__(256) ln_kernel(const float* __restrict__ in,
                                                 const float* __restrict__ w,
                                                 const float* __restrict__ b,
                                                 __nv_bfloat16* __restrict__ ohi,
                                                 __nv_bfloat16* __restrict__ olo)
{
    __shared__ float red[8];
    __shared__ float s_mu, s_rs;
    int row = blockIdx.x;
    int tid = threadIdx.x;
    const float4* ip = (const float4*)(in + (size_t)row * EMBED);
    float4 v = ip[tid];

    float s = v.x + v.y + v.z + v.w;
    #pragma unroll
    for (int o = 16; o; o >>= 1) s += __shfl_xor_sync(0xffffffffu, s, o);
    if ((tid & 31) == 0) red[tid >> 5] = s;
    __syncthreads();
    if (tid == 0) {
        float tot = 0.f;
        #pragma unroll
        for (int i = 0; i < 8; i++) tot += red[i];
        s_mu = tot * (1.0f / EMBED);
    }
    __syncthreads();
    float mu = s_mu;

    float dx = v.x - mu, dy = v.y - mu, dz = v.z - mu, dw = v.w - mu;
    float s2 = dx*dx + dy*dy + dz*dz + dw*dw;
    #pragma unroll
    for (int o = 16; o; o >>= 1) s2 += __shfl_xor_sync(0xffffffffu, s2, o);
    __syncthreads();
    if ((tid & 31) == 0) red[tid >> 5] = s2;
    __syncthreads();
    if (tid == 0) {
        float tot = 0.f;
        #pragma unroll
        for (int i = 0; i < 8; i++) tot += red[i];
        s_rs = rsqrtf(tot * (1.0f / EMBED) + EPS);
    }
    __syncthreads();
    float rs = s_rs;

    float4 wv = ((const float4*)w)[tid];
    float4 bv = ((const float4*)b)[tid];
    float ox = dx * rs * wv.x + bv.x;
    float oy = dy * rs * wv.y + bv.y;
    float oz = dz * rs * wv.z + bv.z;
    float ow = dw * rs * wv.w + bv.w;
    uint2 ph, pl;
    split4(ox, oy, oz, ow, ph, pl);
    size_t base = (size_t)row * EMBED + tid * 4;
    *(uint2*)(ohi + base) = ph;
    *(uint2*)(olo + base) = pl;
}

// ================= HMMA GEMM (NT, bf16x3 split, fp32 accum) =================
// EPI: 0 = bias (fp32), 1 = bias + residual (fp32), 2 = bias + gelu (bf16 hi/lo),
//      3 = bias + q-scale for cols<1024 (bf16 hi/lo)   [qkv projection]
#define TILEB 16384   // 128 rows * 128 bytes

template<int EPI>
__global__ void __launch_bounds__(256, 1) mm_kernel(
    const __nv_bfloat16* __restrict__ Ahi, const __nv_bfloat16* __restrict__ Alo,
    const __nv_bfloat16* __restrict__ Bhi, const __nv_bfloat16* __restrict__ Blo,
    const float* __restrict__ bias, const float* __restrict__ res,
    float* __restrict__ C,
    __nv_bfloat16* __restrict__ Chi, __nv_bfloat16* __restrict__ Clo,
    int M, int N, int K)
{
    extern __shared__ char smem[];   // 2 stages * 4 tiles * 16KB = 128KB
    uint32_t sb = smem_u32(smem);
    int tid = threadIdx.x;
    int bm = blockIdx.x * 128;
    int bn = blockIdx.y * 128;
    int lane = tid & 31, w = tid >> 5;
    int wm = w & 1, wn = w >> 1;     // warp grid 2(m) x 4(n)

    int cc = tid & 7;
    int r0 = tid >> 3;
    const char* pAh = (const char*)(Ahi + (size_t)(bm + r0) * K) + cc * 16;
    const char* pAl = (const char*)(Alo + (size_t)(bm + r0) * K) + cc * 16;
    const char* pBh = (const char*)(Bhi + (size_t)(bn + r0) * K) + cc * 16;
    const char* pBl = (const char*)(Blo + (size_t)(bn + r0) * K) + cc * 16;
    size_t rowblk = (size_t)K * 64;  // 32 rows * K * 2B

    float acc[4][4][4];
    #pragma unroll
    for (int i = 0; i < 4; i++)
        #pragma unroll
        for (int j = 0; j < 4; j++)
            #pragma unroll
            for (int q = 0; q < 4; q++) acc[i][j][q] = 0.f;

    int nCh = K >> 6;

    {
        uint32_t st = sb;
        #pragma unroll
        for (int j = 0; j < 4; j++) {
            uint32_t d = SWZ((uint32_t)((r0 + 32*j) * 128 + cc * 16));
            size_t so = (size_t)j * rowblk;
            CP16(st + 0*TILEB + d, pAh + so);
            CP16(st + 1*TILEB + d, pAl + so);
            CP16(st + 2*TILEB + d, pBh + so);
            CP16(st + 3*TILEB + d, pBl + so);
        }
        CP_COMMIT();
    }

    for (int c = 0; c < nCh; c++) {
        if (c + 1 < nCh) {
            uint32_t st = sb + (uint32_t)((c + 1) & 1) * (4 * TILEB);
            size_t koff = (size_t)(c + 1) * 128;
            #pragma unroll
            for (int j = 0; j < 4; j++) {
                uint32_t d = SWZ((uint32_t)((r0 + 32*j) * 128 + cc * 16));
                size_t so = (size_t)j * rowblk + koff;
                CP16(st + 0*TILEB + d, pAh + so);
                CP16(st + 1*TILEB + d, pAl + so);
                CP16(st + 2*TILEB + d, pBh + so);
                CP16(st + 3*TILEB + d, pBl + so);
            }
            CP_COMMIT();
            asm volatile("cp.async.wait_group 1;" ::: "memory");
        } else {
            asm volatile("cp.async.wait_group 0;" ::: "memory");
        }
        __syncthreads();

        uint32_t st = sb + (uint32_t)(c & 1) * (4 * TILEB);
        uint32_t Ahs = st, Als = st + TILEB, Bhs = st + 2*TILEB, Bls = st + 3*TILEB;

        #pragma unroll
        for (int ks = 0; ks < 4; ks++) {
            uint32_t ahi[4][4], alo[4][4], bhi[4][2], blo[4][2];
            #pragma unroll
            for (int i = 0; i < 4; i++) {
                int row = wm*64 + i*16 + (lane & 15);
                int c16 = ks*2 + (lane >> 4);
                uint32_t off = SWZ((uint32_t)(row * 128 + c16 * 16));
                ldsm_x4(Ahs + off, ahi[i][0], ahi[i][1], ahi[i][2], ahi[i][3]);
                ldsm_x4(Als + off, alo[i][0], alo[i][1], alo[i][2], alo[i][3]);
            }
            #pragma unroll
            for (int jj = 0; jj < 2; jj++) {
                int row = wn*32 + jj*16 + (lane & 7) + (((lane >> 4) & 1) << 3);
                int c16 = ks*2 + ((lane >> 3) & 1);
                uint32_t off = SWZ((uint32_t)(row * 128 + c16 * 16));
                uint32_t t0, t1, t2, t3;
                ldsm_x4(Bhs + off, t0, t1, t2, t3);
                bhi[jj*2][0] = t0; bhi[jj*2][1] = t1;
                bhi[jj*2+1][0] = t2; bhi[jj*2+1][1] = t3;
                ldsm_x4(Bls + off, t0, t1, t2, t3);
                blo[jj*2][0] = t0; blo[jj*2][1] = t1;
                blo[jj*2+1][0] = t2; blo[jj*2+1][1] = t3;
            }
            #pragma unroll
            for (int i = 0; i < 4; i++)
                #pragma unroll
                for (int j = 0; j < 4; j++)
                    mma16816(acc[i][j], ahi[i], bhi[j]);
            #pragma unroll
            for (int i = 0; i < 4; i++)
                #pragma unroll
                for (int j = 0; j < 4; j++)
                    mma16816(acc[i][j], ahi[i], blo[j]);
            #pragma unroll
            for (int i = 0; i < 4; i++)
                #pragma unroll
                for (int j = 0; j < 4; j++)
                    mma16816(acc[i][j], alo[i], bhi[j]);
        }
        __syncthreads();
    }

    // ---- epilogue ----
    int mrow = bm + wm*64;
    int ncol = bn + wn*32;
    #pragma unroll
    for (int i = 0; i < 4; i++) {
        #pragma unroll
        for (int j = 0; j < 4; j++) {
            int rg = mrow + i*16 + (lane >> 2);
            int cg = ncol + j*8 + 2*(lane & 3);
            float b0v = bias[cg], b1v = bias[cg + 1];
            float v0 = acc[i][j][0] + b0v, v1 = acc[i][j][1] + b1v;
            float v2 = acc[i][j][2] + b0v, v3 = acc[i][j][3] + b1v;
            size_t a0 = (size_t)rg * N + cg;
            size_t a1 = (size_t)(rg + 8) * N + cg;
            if (EPI == 1) {
                float2 q0 = *(const float2*)(res + a0);
                float2 q1 = *(const float2*)(res + a1);
                v0 += q0.x; v1 += q0.y; v2 += q1.x; v3 += q1.y;
            }
            if (EPI == 2) {
                v0 = 0.5f * v0 * (1.0f + erff(v0 * 0.70710678118654752f));
                v1 = 0.5f * v1 * (1.0f + erff(v1 * 0.70710678118654752f));
                v2 = 0.5f * v2 * (1.0f + erff(v2 * 0.70710678118654752f));
                v3 = 0.5f * v3 * (1.0f + erff(v3 * 0.70710678118654752f));
            }
            if (EPI == 3) {
                float sc = (cg < EMBED) ? QSCALE : 1.0f;
                v0 *= sc; v1 *= sc; v2 *= sc; v3 *= sc;
            }
            if (EPI == 2 || EPI == 3) {
                uint32_t ph, pl;
                split2(v0, v1, ph, pl);
                *(uint32_t*)(Chi + a0) = ph;
                *(uint32_t*)(Clo + a0) = pl;
                split2(v2, v3, ph, pl);
                *(uint32_t*)(Chi + a1) = ph;
                *(uint32_t*)(Clo + a1) = pl;
            } else {
                *(float2*)(C + a0) = make_float2(v0, v1);
                *(float2*)(C + a1) = make_float2(v2, v3);
            }
        }
    }
}

// ================= Flash attention (HMMA bf16x3 split, causal, exp2) =================
// CTA: 128 q rows, 64-key tiles. 8 warps, warp = 16 q rows x full 64 keys.
// smem: Qhi 16K | Qlo 16K | 2 stages x {Khi,Klo,Vhi,Vlo} 8K each = 64K. Total 96K.
#define FA_QH 0u
#define FA_QL 16384u
#define FA_ST 32768u
#define FA_STB 32768u
#define KF(arr, j) (&(arr)[(((j) >> 1) << 2) + (((j) & 1) << 1)])

__global__ void __launch_bounds__(256) fattn_kernel(
    const __nv_bfloat16* __restrict__ qkv_hi,
    const __nv_bfloat16* __restrict__ qkv_lo,
    __nv_bfloat16* __restrict__ ohi,
    __nv_bfloat16* __restrict__ olo)
{
    extern __shared__ char sm_[];
    uint32_t sb = smem_u32(sm_);
    int tid = threadIdx.x, lane = tid & 31, w = tid >> 5;
    int qblk = blockIdx.x, h = blockIdx.y, b = blockIdx.z;
    int q0 = qblk * 128;
    int ntiles = 2 * (qblk + 1);

    int cc = tid & 7, rr = tid >> 3;   // chunk 0..7, row 0..31
    const char* base_h = (const char*)qkv_hi + ((size_t)(b*SEQ)*3072 + h*64 + cc*8) * 2;
    const char* base_l = (const char*)qkv_lo + ((size_t)(b*SEQ)*3072 + h*64 + cc*8) * 2;

    // ---- Q load (rows q0..q0+127) ----
    #pragma unroll
    for (int i = 0; i < 4; i++) {
        int r = rr + 32*i;
        size_t go = (size_t)(q0 + r) * 6144;
        uint32_t d = SWZ((uint32_t)(r * 128 + cc * 16));
        CP16(sb + FA_QH + d, base_h + go);
        CP16(sb + FA_QL + d, base_l + go);
    }
    CP_COMMIT();

    // ---- prefetch K/V tile 0 ----
    {
        uint32_t st = sb + FA_ST;
        #pragma unroll
        for (int i = 0; i < 2; i++) {
            int r = rr + 32*i;
            size_t go = (size_t)r * 6144;
            uint32_t d = SWZ((uint32_t)(r * 128 + cc * 16));
            CP16(st + 0     + d, base_h + go + 2048);   // K hi (+1024 elems)
            CP16(st + 8192  + d, base_l + go + 2048);   // K lo
            CP16(st + 16384 + d, base_h + go + 4096);   // V hi (+2048 elems)
            CP16(st + 24576 + d, base_l + go + 4096);   // V lo
        }
        CP_COMMIT();
    }

    asm volatile("cp.async.wait_group 1;" ::: "memory");  // Q done
    __syncthreads();

    // ---- Q fragments ----
    uint32_t qh[4][4], ql[4][4];
    #pragma unroll
    for (int ks = 0; ks < 4; ks++) {
        int row = w*16 + (lane & 15);
        int c16 = ks*2 + (lane >> 4);
        uint32_t off = SWZ((uint32_t)(row * 128 + c16 * 16));
        ldsm_x4(sb + FA_QH + off, qh[ks][0], qh[ks][1], qh[ks][2], qh[ks][3]);
        ldsm_x4(sb + FA_QL + off, ql[ks][0], ql[ks][1], ql[ks][2], ql[ks][3]);
    }

    float o[8][4];
    #pragma unroll
    for (int j = 0; j < 8; j++)
        #pragma unroll
        for (int q = 0; q < 4; q++) o[j][q] = 0.f;
    float m0 = -INFINITY, m1 = -INFINITY, l0 = 0.f, l1 = 0.f;
    int qg0 = q0 + w*16 + (lane >> 2);
    int qg1 = qg0 + 8;
    int wmin = q0 + w*16, wmax = wmin + 15;

    for (int kt = 0; kt < ntiles; kt++) {
        int k0 = kt * 64;
        if (kt + 1 < ntiles) {
            uint32_t st = sb + FA_ST + (uint32_t)((kt + 1) & 1) * FA_STB;
            #pragma unroll
            for (int i = 0; i < 2; i++) {
                int r = rr + 32*i;
                size_t go = (size_t)((kt + 1) * 64 + r) * 6144;
                uint32_t d = SWZ((uint32_t)(r * 128 + cc * 16));
                CP16(st + 0     + d, base_h + go + 2048);
                CP16(st + 8192  + d, base_l + go + 2048);
                CP16(st + 16384 + d, base_h + go + 4096);
                CP16(st + 24576 + d, base_l + go + 4096);
            }
            CP_COMMIT();
            asm volatile("cp.async.wait_group 1;" ::: "memory");
        } else {
            asm volatile("cp.async.wait_group 0;" ::: "memory");
        }
        __syncthreads();

        if (k0 <= wmax) {   // warp has at least one unmasked column
            uint32_t st = sb + FA_ST + (uint32_t)(kt & 1) * FA_STB;

            // ---- S = Q @ K^T (3-product split) ----
            float s[8][4];
            #pragma unroll
            for (int j = 0; j < 8; j++)
                #pragma unroll
                for (int q = 0; q < 4; q++) s[j][q] = 0.f;

            #pragma unroll
            for (int ks = 0; ks < 4; ks++) {
                uint32_t kh[16], kl[16];
                #pragma unroll
                for (int jj = 0; jj < 4; jj++) {
                    int row = jj*16 + (lane & 7) + (((lane >> 4) & 1) << 3);
                    int c16 = ks*2 + ((lane >> 3) & 1);
                    uint32_t off = SWZ((uint32_t)(row * 128 + c16 * 16));
                    ldsm_x4(st + off,        kh[jj*4], kh[jj*4+1], kh[jj*4+2], kh[jj*4+3]);
                    ldsm_x4(st + 8192 + off, kl[jj*4], kl[jj*4+1], kl[jj*4+2], kl[jj*4+3]);
                }
                #pragma unroll
                for (int j = 0; j < 8; j++) mma16816(s[j], qh[ks], KF(kh, j));
                #pragma unroll
                for (int j = 0; j < 8; j++) mma16816(s[j], qh[ks], KF(kl, j));
                #pragma unroll
                for (int j = 0; j < 8; j++) mma16816(s[j], ql[ks], KF(kh, j));
            }

            // ---- causal mask ----
            if (k0 + 63 > wmin) {
                int cb = k0 + 2*(lane & 3);
                #pragma unroll
                for (int j = 0; j < 8; j++) {
                    int c0 = cb + j*8, c1 = c0 + 1;
                    if (c0 > qg0) s[j][0] = -INFINITY;
                    if (c1 > qg0) s[j][1] = -INFINITY;
                    if (c0 > qg1) s[j][2] = -INFINITY;
                    if (c1 > qg1) s[j][3] = -INFINITY;
                }
            }

            // ---- online softmax (base-2) ----
            float tm0 = s[0][0], tm1 = s[0][2];
            #pragma unroll
            for (int j = 0; j < 8; j++) {
                tm0 = fmaxf(tm0, fmaxf(s[j][0], s[j][1]));
                tm1 = fmaxf(tm1, fmaxf(s[j][2], s[j][3]));
            }
            tm0 = fmaxf(tm0, __shfl_xor_sync(0xffffffffu, tm0, 1));
            tm0 = fmaxf(tm0, __shfl_xor_sync(0xffffffffu, tm0, 2));
            tm1 = fmaxf(tm1, __shfl_xor_sync(0xffffffffu, tm1, 1));
            tm1 = fmaxf(tm1, __shfl_xor_sync(0xffffffffu, tm1, 2));

            float nm0 = fmaxf(m0, tm0), nm1 = fmaxf(m1, tm1);
            float a0 = ex2f(m0 - nm0), a1 = ex2f(m1 - nm1);
            m0 = nm0; m1 = nm1;

            float sum0 = 0.f, sum1 = 0.f;
            #pragma unroll
            for (int j = 0; j < 8; j++) {
                s[j][0] = ex2f(s[j][0] - nm0); sum0 += s[j][0];
                s[j][1] = ex2f(s[j][1] - nm0); sum0 += s[j][1];
                s[j][2] = ex2f(s[j][2] - nm1); sum1 += s[j][2];
                s[j][3] = ex2f(s[j][3] - nm1); sum1 += s[j][3];
            }
            sum0 += __shfl_xor_sync(0xffffffffu, sum0, 1);
            sum0 += __shfl_xor_sync(0xffffffffu, sum0, 2);
            sum1 += __shfl_xor_sync(0xffffffffu, sum1, 1);
            sum1 += __shfl_xor_sync(0xffffffffu, sum1, 2);
            l0 = l0 * a0 + sum0;
            l1 = l1 * a1 + sum1;

            #pragma unroll
            for (int j = 0; j < 8; j++) {
                o[j][0] *= a0; o[j][1] *= a0;
                o[j][2] *= a1; o[j][3] *= a1;
            }

            // ---- P fragments (hi/lo) ----
            uint32_t ph[4][4], pl[4][4];
            #pragma unroll
            for (int ks = 0; ks < 4; ks++) {
                split2(s[2*ks][0],   s[2*ks][1],   ph[ks][0], pl[ks][0]);
                split2(s[2*ks][2],   s[2*ks][3],   ph[ks][1], pl[ks][1]);
                split2(s[2*ks+1][0], s[2*ks+1][1], ph[ks][2], pl[ks][2]);
                split2(s[2*ks+1][2], s[2*ks+1][3], ph[ks][3], pl[ks][3]);
            }

            // ---- O += P @ V (3-product split) ----
            #pragma unroll
            for (int ks = 0; ks < 4; ks++) {
                uint32_t vh[16], vl[16];
                #pragma unroll
                for (int nn = 0; nn < 4; nn++) {
                    int key = ks*16 + (lane & 7) + (((lane >> 3) & 1) << 3);
                    int dim = nn*16 + ((lane >> 4) << 3);
                    uint32_t off = SWZ((uint32_t)(key * 128 + dim * 2));
                    ldsm_x4_t(st + 16384 + off, vh[nn*4], vh[nn*4+1], vh[nn*4+2], vh[nn*4+3]);
                    ldsm_x4_t(st + 24576 + off, vl[nn*4], vl[nn*4+1], vl[nn*4+2], vl[nn*4+3]);
                }
                #pragma unroll
                for (int j = 0; j < 8; j++) mma16816(o[j], ph[ks], KF(vh, j));
                #pragma unroll
                for (int j = 0; j < 8; j++) mma16816(o[j], pl[ks], KF(vh, j));
                #pragma unroll
                for (int j = 0; j < 8; j++) mma16816(o[j], ph[ks], KF(vl, j));
            }
        }
        __syncthreads();
    }

    // ---- epilogue: O/l -> bf16 hi/lo ----
    float inv0 = 1.0f / l0, inv1 = 1.0f / l1;
    size_t t0 = (size_t)(b*SEQ + qg0) * EMBED + h*64;
    size_t t1 = t0 + (size_t)8 * EMBED;
    #pragma unroll
    for (int j = 0; j < 8; j++) {
        int dd = j*8 + 2*(lane & 3);
        uint32_t hh, ll;
        split2(o[j][0]*inv0, o[j][1]*inv0, hh, ll);
        *(uint32_t*)(ohi + t0 + dd) = hh;
        *(uint32_t*)(olo + t0 + dd) = ll;
        split2(o[j][2]*inv1, o[j][3]*inv1, hh, ll);
        *(uint32_t*)(ohi + t1 + dd) = hh;
        *(uint32_t*)(olo + t1 + dd) = ll;
    }
}

// ================= launch =================
extern "C" void kernel_launch(void* const* d_in, const int* in_sizes, int n_in,
                              void* d_out, int out_size)
{
    const float* x      = (const float*)d_in[0];
    const float* ln1_w  = (const float*)d_in[1];
    const float* ln1_b  = (const float*)d_in[2];
    const float* qkv_w  = (const float*)d_in[3];
    const float* qkv_b  = (const float*)d_in[4];
    const float* proj_w = (const float*)d_in[5];
    const float* proj_b = (const float*)d_in[6];
    const float* ln2_w  = (const float*)d_in[7];
    const float* ln2_b  = (const float*)d_in[8];
    const float* fc1_w  = (const float*)d_in[9];
    const float* fc1_b  = (const float*)d_in[10];
    const float* fc2_w  = (const float*)d_in[11];
    const float* fc2_b  = (const float*)d_in[12];
    float* out = (float*)d_out;

    float *x1;
    __nv_bfloat16 *xn_hi, *xn_lo, *qkv_hi, *qkv_lo, *att_hi, *att_lo, *h_hi, *h_lo;
    __nv_bfloat16 *qw_hi, *qw_lo, *pw_hi, *pw_lo, *f1_hi, *f1_lo, *f2_hi, *f2_lo;
    cudaGetSymbolAddress((void**)&x1,     g_x1);
    cudaGetSymbolAddress((void**)&xn_hi,  g_xn_hi);
    cudaGetSymbolAddress((void**)&xn_lo,  g_xn_lo);
    cudaGetSymbolAddress((void**)&qkv_hi, g_qkv_hi);
    cudaGetSymbolAddress((void**)&qkv_lo, g_qkv_lo);
    cudaGetSymbolAddress((void**)&att_hi, g_att_hi);
    cudaGetSymbolAddress((void**)&att_lo, g_att_lo);
    cudaGetSymbolAddress((void**)&h_hi,   g_h_hi);
    cudaGetSymbolAddress((void**)&h_lo,   g_h_lo);
    cudaGetSymbolAddress((void**)&qw_hi,  g_qkvw_hi);
    cudaGetSymbolAddress((void**)&qw_lo,  g_qkvw_lo);
    cudaGetSymbolAddress((void**)&pw_hi,  g_projw_hi);
    cudaGetSymbolAddress((void**)&pw_lo,  g_projw_lo);
    cudaGetSymbolAddress((void**)&f1_hi,  g_fc1w_hi);
    cudaGetSymbolAddress((void**)&f1_lo,  g_fc1w_lo);
    cudaGetSymbolAddress((void**)&f2_hi,  g_fc2w_hi);
    cudaGetSymbolAddress((void**)&f2_lo,  g_fc2w_lo);

    int gemm_smem = 2 * 4 * TILEB;   // 131072
    cudaFuncSetAttribute(mm_kernel<0>, cudaFuncAttributeMaxDynamicSharedMemorySize, gemm_smem);
    cudaFuncSetAttribute(mm_kernel<1>, cudaFuncAttributeMaxDynamicSharedMemorySize, gemm_smem);
    cudaFuncSetAttribute(mm_kernel<2>, cudaFuncAttributeMaxDynamicSharedMemorySize, gemm_smem);
    cudaFuncSetAttribute(mm_kernel<3>, cudaFuncAttributeMaxDynamicSharedMemorySize, gemm_smem);
    int attn_smem = 96 * 1024;
    cudaFuncSetAttribute(fattn_kernel, cudaFuncAttributeMaxDynamicSharedMemorySize, attn_smem);

    // weight conversion
    cvt_kernel<<<(3*EMBED*EMBED/4 + 255)/256, 256>>>(qkv_w,  qw_hi, qw_lo, 3*EMBED*EMBED/4);
    cvt_kernel<<<(EMBED*EMBED/4   + 255)/256, 256>>>(proj_w, pw_hi, pw_lo, EMBED*EMBED/4);
    cvt_kernel<<<(HIDDEN*EMBED/4  + 255)/256, 256>>>(fc1_w,  f1_hi, f1_lo, HIDDEN*EMBED/4);
    cvt_kernel<<<(EMBED*HIDDEN/4  + 255)/256, 256>>>(fc2_w,  f2_hi, f2_lo, EMBED*HIDDEN/4);

    // 1. LN1 -> xn hi/lo
    ln_kernel<<<NTOK, 256>>>(x, ln1_w, ln1_b, xn_hi, xn_lo);
    // 2. qkv = xn @ qkv_w^T + qkv_b  (q pre-scaled, bf16 hi/lo)
    mm_kernel<3><<<dim3(NTOK/128, 3*EMBED/128), 256, gemm_smem>>>(
        xn_hi, xn_lo, qw_hi, qw_lo, qkv_b, nullptr, nullptr, qkv_hi, qkv_lo,
        NTOK, 3*EMBED, EMBED);
    // 3. attention -> att hi/lo
    fattn_kernel<<<dim3(SEQ/128, HEADS, BATCH), 256, attn_smem>>>(qkv_hi, qkv_lo, att_hi, att_lo);
    // 4. x1 = att @ proj_w^T + proj_b + x  (fp32)
    mm_kernel<1><<<dim3(NTOK/128, EMBED/128), 256, gemm_smem>>>(
        att_hi, att_lo, pw_hi, pw_lo, proj_b, x, x1, nullptr, nullptr,
        NTOK, EMBED, EMBED);
    // 5. LN2 -> xn hi/lo
    ln_kernel<<<NTOK, 256>>>(x1, ln2_w, ln2_b, xn_hi, xn_lo);
    // 6. h = gelu(xn @ fc1_w^T + fc1_b) -> bf16 hi/lo
    mm_kernel<2><<<dim3(NTOK/128, HIDDEN/128), 256, gemm_smem>>>(
        xn_hi, xn_lo, f1_hi, f1_lo, fc1_b, nullptr, nullptr, h_hi, h_lo,
        NTOK, HIDDEN, EMBED);
    // 7. out = h @ fc2_w^T + fc2_b + x1  (fp32)
    mm_kernel<1><<<dim3(NTOK/128, EMBED/128), 256, gemm_smem>>>(
        h_hi, h_lo, f2_hi, f2_lo, fc2_b, x1, out, nullptr, nullptr,
        NTOK, EMBED, HIDDEN);
}